// round 8
// baseline (speedup 1.0000x reference)
#include <cuda_runtime.h>
#include <math_constants.h>

// Shapes (fixed by problem)
#define B 32
#define T 512
#define D 512
#define H 8
#define S 196
#define LAYER_ID 2
#define K_TOP 51   // int(0.1 * 512)
#define NBLK 8     // blocks per batch
#define CHUNK 64   // t's per block
#define NG 16      // partial groups (NBLK x 2 subgroups)

// Scratch (allocation-free rule: __device__ globals; zero-initialized)
__device__ float g_w[B * T];
__device__ float g_part[B][NG][S];
__device__ int   g_warr[B];   // weights-ready arrivals per batch
__device__ int   g_sync[B];   // gather-done arrivals per batch

__device__ __forceinline__ float ldcg(const float* p) {
    float v; asm volatile("ld.global.cg.f32 %0, [%1];" : "=f"(v) : "l"(p));
    return v;
}

// ---------------------------------------------------------------------------
// Single fused kernel. grid (NBLK, B), 512 threads, full co-residency
// (launch_bounds(512,2) -> <=64 regs -> 296 block slots >= 256 blocks).
// Phase A: this block computes cosine weights for its 64-t chunk.
// Per-batch release/acquire rendezvous (threadfence + counter + spin).
// Phase B: chunk-local stable rank counting -> select rank<m -> gather its
// selected attn rows -> partials; last-arriving block per b merges+normalizes.
// ---------------------------------------------------------------------------
__global__ __launch_bounds__(512, 2) void k_all(
    const float* __restrict__ fore,     // (B, D)
    const float* __restrict__ embed,    // (B, T, D)
    const int*   __restrict__ targets,  // (B, T+1) int32
    const float* __restrict__ attns,    // (L, B, H, T, S)
    float*       __restrict__ out)      // (B, S)
{
    __shared__ unsigned long long keys[T];   // 4 KB
    __shared__ int   rank[CHUNK];
    __shared__ int   sl[CHUNK];
    __shared__ float slw[CHUNK];
    __shared__ int   s_last;
    __shared__ float rmin[256], rmax[256];
    __shared__ float s_mn, s_mx;

    const int c    = blockIdx.x;   // 0..NBLK-1
    const int b    = blockIdx.y;
    const int tid  = threadIdx.x;  // 0..511
    const int lane = tid & 31;
    const int warp = tid >> 5;     // 0..15, each warp: 4 t's of the chunk

    // ================= Phase A: cosine weights for chunk c =================
    {
        const float4* yrow = reinterpret_cast<const float4*>(fore + (size_t)b * D);
        float4 yv[4];
#pragma unroll
        for (int i = 0; i < 4; i++) yv[i] = __ldg(&yrow[lane + i * 32]);
        float ys = 0.f;
#pragma unroll
        for (int i = 0; i < 4; i++) {
            float4 y = yv[i];
            ys += y.x * y.x + y.y * y.y + y.z * y.z + y.w * y.w;
        }
#pragma unroll
        for (int o = 16; o; o >>= 1) ys += __shfl_xor_sync(0xffffffffu, ys, o);
        const float yn = fmaxf(sqrtf(ys), 1e-8f);

#pragma unroll
        for (int pass = 0; pass < 2; pass++) {
            const int t0 = c * CHUNK + warp * 4 + pass * 2;
            const float4* x0 = reinterpret_cast<const float4*>(embed + ((size_t)b * T + t0) * D);
            const float4* x1 = x0 + D / 4;
            float4 xa[4], xb[4];
#pragma unroll
            for (int i = 0; i < 4; i++) {
                xa[i] = __ldg(&x0[lane + i * 32]);
                xb[i] = __ldg(&x1[lane + i * 32]);
            }
            float n0 = 0.f, n1 = 0.f, xs0 = 0.f, xs1 = 0.f;
#pragma unroll
            for (int i = 0; i < 4; i++) {
                float4 y = yv[i], a = xa[i], cc = xb[i];
                n0  += a.x * y.x + a.y * y.y + a.z * y.z + a.w * y.w;
                xs0 += a.x * a.x + a.y * a.y + a.z * a.z + a.w * a.w;
                n1  += cc.x * y.x + cc.y * y.y + cc.z * y.z + cc.w * y.w;
                xs1 += cc.x * cc.x + cc.y * cc.y + cc.z * cc.z + cc.w * cc.w;
            }
#pragma unroll
            for (int o = 16; o; o >>= 1) {
                n0  += __shfl_xor_sync(0xffffffffu, n0,  o);
                n1  += __shfl_xor_sync(0xffffffffu, n1,  o);
                xs0 += __shfl_xor_sync(0xffffffffu, xs0, o);
                xs1 += __shfl_xor_sync(0xffffffffu, xs1, o);
            }
            if (lane < 2) {
                const int t = t0 + lane;
                float num = lane ? n1 : n0;
                float xn2 = lane ? xs1 : xs0;
                float xn  = fmaxf(sqrtf(xn2), 1e-8f);
                float wv  = num / (xn * yn);
                int tv    = targets[b * (T + 1) + t];
                bool msk  = (t == 0) || (tv > 0);
                g_w[b * T + t] = msk ? wv : -1.0f;
            }
        }
    }

    // ---- per-batch rendezvous: release own chunk, wait for all 8 ----
    __threadfence();
    __syncthreads();
    if (tid == 0) {
        atomicAdd(&g_warr[b], 1);
        volatile int* va = g_warr;
        while (va[b] < NBLK) { __nanosleep(32); }
    }
    __syncthreads();
    __threadfence();   // acquire

    // ================= Phase B: keys + m =================
    float w = ldcg(&g_w[b * T + tid]);
    unsigned uf = __float_as_uint(w);
    uf = (uf & 0x80000000u) ? ~uf : (uf | 0x80000000u);
    keys[tid] = ((unsigned long long)uf << 32) | (unsigned)(T - 1 - tid);
    if (tid < CHUNK) rank[tid] = 0;

    int tv  = targets[b * (T + 1) + tid];
    int cnt = __syncthreads_count((tid == 0) || (tv > 0));
    int m   = (int)ceilf((float)cnt * 0.1f);
    m = m < K_TOP ? m : K_TOP;

    // ---- chunk-local rank counting: 8 threads per t, disjoint 64-key slices
    {
        const int tl    = tid & (CHUNK - 1);
        const int piece = tid >> 6;
        const unsigned long long mykey = keys[c * CHUNK + tl];
        const unsigned long long* kp = keys + piece * 64;
        int r = 0;
#pragma unroll 8
        for (int i = 0; i < 64; i++) r += (kp[i] > mykey);
        atomicAdd(&rank[tl], r);
    }
    __syncthreads();

    // ---- selected list for this chunk, t-order (deterministic)
    if (tid < CHUNK && rank[tid] < m) {
        int pos = 0;
        for (int i = 0; i < tid; i++) pos += (rank[i] < m);
        sl[pos] = tid;
        unsigned hu = (unsigned)(keys[c * CHUNK + tid] >> 32);
        unsigned orig = (hu & 0x80000000u) ? (hu ^ 0x80000000u) : ~hu;
        slw[pos] = __uint_as_float(orig);
    }
    int ns = __syncthreads_count((tid < CHUNK) ? (rank[tid] < m) : 0);

    // ---- gather selected rows, 2 s-subgroups
    const int jsub = tid / S;          // 0,1 active; tid >= 392 idle
    const int s    = tid - jsub * S;
    if (jsub < 2) {
        const float* base = attns + ((size_t)(LAYER_ID * B + b)) * H * T * S + s;
        float acc = 0.f;
        for (int i = jsub; i < ns; i += 4) {
            int i2 = i + 2;
            bool a2 = (i2 < ns);
            int   t0i = c * CHUNK + sl[i];
            int   t1i = a2 ? (c * CHUNK + sl[i2]) : t0i;
            float w0  = slw[i];
            float w1  = a2 ? slw[i2] : 0.f;
            const float* p0 = base + (size_t)t0i * S;
            const float* p1 = base + (size_t)t1i * S;
            float v0[8], v1[8];
#pragma unroll
            for (int h = 0; h < H; h++) {
                v0[h] = __ldg(p0 + (size_t)h * T * S);
                v1[h] = __ldg(p1 + (size_t)h * T * S);
            }
            float h0 = 0.f, h1 = 0.f;
#pragma unroll
            for (int h = 0; h < H; h++) { h0 += v0[h]; h1 += v1[h]; }
            acc += fmaxf(w0 * (h0 * 0.125f), 0.f);
            if (a2) acc += fmaxf(w1 * (h1 * 0.125f), 0.f);
        }
        g_part[b][c * 2 + jsub][s] = acc;
    }

    // ---- arrival; last block per b merges + normalizes + resets counters
    __threadfence();
    __syncthreads();
    if (tid == 0) {
        int done = atomicAdd(&g_sync[b], 1);
        s_last = (done == NBLK - 1);
    }
    __syncthreads();
    if (!s_last) return;
    if (tid == 0) { g_sync[b] = 0; g_warr[b] = 0; }   // reset for next replay
    __threadfence();

    float acc = 0.f;
    const bool active = (tid < S);
    if (active) {
#pragma unroll
        for (int g2 = 0; g2 < NG; g2++) acc += ldcg(&g_part[b][g2][tid]);
        acc /= (float)m;
    }
    if (tid < 256) {
        rmin[tid] = active ? acc :  CUDART_INF_F;
        rmax[tid] = active ? acc : -CUDART_INF_F;
    }
    __syncthreads();
    for (int o = 128; o > 0; o >>= 1) {
        if (tid < o) {
            rmin[tid] = fminf(rmin[tid], rmin[tid + o]);
            rmax[tid] = fmaxf(rmax[tid], rmax[tid + o]);
        }
        __syncthreads();
    }
    if (tid == 0) { s_mn = rmin[0]; s_mx = rmax[0]; }
    __syncthreads();

    if (active)
        out[b * S + tid] = (acc - s_mn) / fmaxf(s_mx - s_mn, 1e-12f);
}

// ---------------------------------------------------------------------------
extern "C" void kernel_launch(void* const* d_in, const int* in_sizes, int n_in,
                              void* d_out, int out_size)
{
    const float* fore    = (const float*)d_in[0];  // (B, D)
    const float* embed   = (const float*)d_in[1];  // (B, T, D)
    const float* attns   = (const float*)d_in[2];  // (L, B, H, T, S)
    const int*   targets = (const int*)  d_in[3];  // (B, T+1) int32
    float* out = (float*)d_out;

    k_all<<<dim3(NBLK, B), 512>>>(fore, embed, targets, attns, out);
}